// round 15
// baseline (speedup 1.0000x reference)
#include <cuda_runtime.h>
#include <cuda_fp16.h>
#include <cstdint>

// ---------------- scratch (static device globals; no allocation) ------------
__device__ __half g_xh [(size_t)100000 * 128];
__device__ __half g_agg[(size_t)100000 * 128];
__device__ __half g_h1 [(size_t)100000 * 128];
__device__ __half g_h2 [(size_t)100000 * 128];
__device__ int   g_deg   [100002];
__device__ int   g_rowptr[100002];
__device__ int   g_cursor[100002];
__device__ int   g_csr   [1700000];
__device__ int   g_bsum  [128];
__device__ int   g_boff  [128];
__device__ uint32_t g_wf16[4][8192];   // fragment-ready fp16 weights (half2 packed)
__device__ int   g_idx64;

// ---------------- index dtype detection (parallel) ---------------------------
__global__ void detect_kernel(const unsigned int* __restrict__ w, long long n32) {
    long long nelem = n32 / 2;
    int t = threadIdx.x;
    long long e = ((long long)t * (nelem - 1)) / 255;
    int ok = (t < 256) ? (w[2 * e + 1] == 0u) : 1;
    int all = __syncthreads_and(ok);
    if (t == 0) g_idx64 = all ? 1 : 0;
}

__device__ __forceinline__ int load_idx(const void* p, long long i) {
    if (g_idx64) return (int)((const long long*)p)[i];
    return ((const int*)p)[i];
}

// ---------------- fp16 helpers ------------------------------------------------
__device__ __forceinline__ float4 ld4h(const __half* p) {
    uint2 u = *reinterpret_cast<const uint2*>(p);
    __half2 a = *reinterpret_cast<__half2*>(&u.x);
    __half2 b = *reinterpret_cast<__half2*>(&u.y);
    float2 fa = __half22float2(a), fb = __half22float2(b);
    return make_float4(fa.x, fa.y, fb.x, fb.y);
}

__device__ __forceinline__ void st4h(__half* p, float4 v) {
    __half2 a = __floats2half2_rn(v.x, v.y);
    __half2 b = __floats2half2_rn(v.z, v.w);
    uint2 u;
    u.x = *reinterpret_cast<uint32_t*>(&a);
    u.y = *reinterpret_cast<uint32_t*>(&b);
    *reinterpret_cast<uint2*>(p) = u;
}

// ---------------- merged prep: wtransform + x->fp16 + deg zero ----------------
__global__ void prep_kernel(const float* __restrict__ x, __half* __restrict__ xh, int n2,
                            const float* __restrict__ W0, const float* __restrict__ W1,
                            const float* __restrict__ W2, const float* __restrict__ W3,
                            uint32_t* __restrict__ Wf, int* __restrict__ deg, int ndeg) {
    int gid = blockIdx.x * blockDim.x + threadIdx.x;
    if (gid < 32768) {
        int which = gid >> 13;
        int o = gid & 8191;
        const float* W = (which == 0) ? W0 : (which == 1) ? W1 : (which == 2) ? W2 : W3;
        int lane = o & 31;
        int r    = (o >> 5) & 1;
        int nt   = (o >> 6) & 15;
        int kt   = o >> 10;
        int c = lane >> 2, t = lane & 3;
        int k = kt * 16 + 2 * t + 8 * r;
        int n = nt * 8 + c;
        __half2 v = __floats2half2_rn(W[k * 128 + n], W[(k + 1) * 128 + n]);
        Wf[gid] = *reinterpret_cast<uint32_t*>(&v);
    } else if (gid < 32768 + n2) {
        int i = gid - 32768;
        float2 v = reinterpret_cast<const float2*>(x)[i];
        reinterpret_cast<__half2*>(xh)[i] = __floats2half2_rn(v.x, v.y);
    } else {
        int i = gid - 32768 - n2;
        if (i < ndeg) deg[i] = 0;
    }
}

// ---------------- CSR build (vectorized, no intermediates) --------------------
__global__ void hist_kernel(const void* __restrict__ ei, int E, int* __restrict__ deg) {
    int i = (blockIdx.x * blockDim.x + threadIdx.x) * 4;
    if (i >= E) return;
    if (i + 4 <= E) {
        int d[4];
        if (g_idx64) {
            const longlong2* pd = reinterpret_cast<const longlong2*>((const long long*)ei + E + i);
            longlong2 d01 = pd[0], d23 = pd[1];
            d[0] = (int)d01.x; d[1] = (int)d01.y; d[2] = (int)d23.x; d[3] = (int)d23.y;
        } else {
            int4 dv = *reinterpret_cast<const int4*>((const int*)ei + E + i);
            d[0] = dv.x; d[1] = dv.y; d[2] = dv.z; d[3] = dv.w;
        }
#pragma unroll
        for (int k = 0; k < 4; k++) atomicAdd(&deg[d[k]], 1);
    } else {
        for (int k = 0; i + k < E; k++)
            atomicAdd(&deg[load_idx(ei, (long long)E + i + k)], 1);
    }
}

__global__ void scan_partial_kernel(const int* __restrict__ deg, int N, int CH,
                                    int* __restrict__ bsum) {
    __shared__ int red[256];
    int b = blockIdx.x, t = threadIdx.x;
    int s = b * CH, e = min(s + CH, N);
    int sum = 0;
    for (int i = s + t; i < e; i += 256) sum += deg[i];
    red[t] = sum;
    __syncthreads();
    for (int off = 128; off > 0; off >>= 1) {
        if (t < off) red[t] += red[t + off];
        __syncthreads();
    }
    if (t == 0) bsum[b] = red[0];
}

__global__ void scan_bsum_kernel(const int* __restrict__ bsum, int* __restrict__ boff,
                                 int* __restrict__ rowptr, int N) {
    __shared__ int s[128];
    int t = threadIdx.x;
    s[t] = bsum[t];
    __syncthreads();
    for (int off = 1; off < 128; off <<= 1) {
        int v = (t >= off) ? s[t - off] : 0;
        __syncthreads();
        s[t] += v;
        __syncthreads();
    }
    boff[t] = (t == 0) ? 0 : s[t - 1];
    if (t == 127) rowptr[N] = s[127];
}

__global__ void scan_write_kernel(const int* __restrict__ deg, int N, int CH,
                                  const int* __restrict__ boff,
                                  int* __restrict__ rowptr, int* __restrict__ cursor) {
    __shared__ int ts[256];
    int b = blockIdx.x, t = threadIdx.x;
    int s = b * CH, e = min(s + CH, N);
    int tc = (CH + 255) / 256;
    int ms = s + t * tc, me = min(ms + tc, e);
    int sum = 0;
    for (int i = ms; i < me; i++) sum += deg[i];
    ts[t] = sum;
    __syncthreads();
    for (int off = 1; off < 256; off <<= 1) {
        int v = (t >= off) ? ts[t - off] : 0;
        __syncthreads();
        ts[t] += v;
        __syncthreads();
    }
    int run = boff[b] + ((t == 0) ? 0 : ts[t - 1]);
    for (int i = ms; i < me; i++) {
        rowptr[i] = run;
        cursor[i] = run;
        run += deg[i];
    }
}

__global__ void fill_kernel(const void* __restrict__ ei, int E,
                            int* __restrict__ cursor, int* __restrict__ csr) {
    int i = (blockIdx.x * blockDim.x + threadIdx.x) * 4;
    if (i >= E) return;
    if (i + 4 <= E) {
        int s[4], d[4];
        if (g_idx64) {
            const longlong2* ps = reinterpret_cast<const longlong2*>((const long long*)ei + i);
            const longlong2* pd = reinterpret_cast<const longlong2*>((const long long*)ei + E + i);
            longlong2 s01 = ps[0], s23 = ps[1];
            longlong2 d01 = pd[0], d23 = pd[1];
            s[0] = (int)s01.x; s[1] = (int)s01.y; s[2] = (int)s23.x; s[3] = (int)s23.y;
            d[0] = (int)d01.x; d[1] = (int)d01.y; d[2] = (int)d23.x; d[3] = (int)d23.y;
        } else {
            int4 sv = *reinterpret_cast<const int4*>((const int*)ei + i);
            int4 dv = *reinterpret_cast<const int4*>((const int*)ei + E + i);
            s[0] = sv.x; s[1] = sv.y; s[2] = sv.z; s[3] = sv.w;
            d[0] = dv.x; d[1] = dv.y; d[2] = dv.z; d[3] = dv.w;
        }
#pragma unroll
        for (int k = 0; k < 4; k++)
            csr[atomicAdd(&cursor[d[k]], 1)] = s[k];
    } else {
        for (int k = 0; i + k < E; k++) {
            int sv = load_idx(ei, i + k);
            int dv = load_idx(ei, (long long)E + i + k);
            csr[atomicAdd(&cursor[dv], 1)] = sv;
        }
    }
}

// ---------------- gather (fp16): out[i] = h[i] + sum_{nbrs} h[j] ---------------
__global__ void gather_kernel(const __half* __restrict__ h, const int* __restrict__ csr,
                              const int* __restrict__ rowptr, int N,
                              __half* __restrict__ out) {
    int w = (blockIdx.x * blockDim.x + threadIdx.x) >> 5;
    int lane = threadIdx.x & 31;
    if (w >= N) return;
    int s = rowptr[w];
    int e = rowptr[w + 1];
    int q = lane * 4;
    float4 acc = ld4h(h + (size_t)w * 128 + q);   // self (eps = 0)
    int j = s;
    for (; j + 4 <= e; j += 4) {
        int s0 = csr[j], s1 = csr[j + 1], s2 = csr[j + 2], s3 = csr[j + 3];
        float4 v0 = ld4h(h + (size_t)s0 * 128 + q);
        float4 v1 = ld4h(h + (size_t)s1 * 128 + q);
        float4 v2 = ld4h(h + (size_t)s2 * 128 + q);
        float4 v3 = ld4h(h + (size_t)s3 * 128 + q);
        acc.x += v0.x + v1.x + v2.x + v3.x;
        acc.y += v0.y + v1.y + v2.y + v3.y;
        acc.z += v0.z + v1.z + v2.z + v3.z;
        acc.w += v0.w + v1.w + v2.w + v3.w;
    }
    for (; j < e; j++) {
        float4 v = ld4h(h + (size_t)csr[j] * 128 + q);
        acc.x += v.x; acc.y += v.y; acc.z += v.z; acc.w += v.w;
    }
    st4h(out + (size_t)w * 128 + q, acc);
}

// ---------------- fused MLP (fp16 MMA, 32 rows/warp, B-fragment reuse) --------
__device__ __forceinline__ void mma_f16(float* c, uint32_t a0, uint32_t a1,
                                        uint32_t a2, uint32_t a3,
                                        uint32_t b0, uint32_t b1) {
    asm volatile(
        "mma.sync.aligned.m16n8k16.row.col.f32.f16.f16.f32 "
        "{%0,%1,%2,%3}, {%4,%5,%6,%7}, {%8,%9}, {%0,%1,%2,%3};"
        : "+f"(c[0]), "+f"(c[1]), "+f"(c[2]), "+f"(c[3])
        : "r"(a0), "r"(a1), "r"(a2), "r"(a3), "r"(b0), "r"(b1));
}

#define T_STRIDE 136
#define MLP_SMEM_BYTES (32768 + 32768 + 8 * 32 * T_STRIDE * 2)

__global__ __launch_bounds__(256, 1)
void mlp_fused_kernel(const __half* __restrict__ A,
                      const uint32_t* __restrict__ Wfa, const uint32_t* __restrict__ Wfb,
                      const float* __restrict__ ba, const float* __restrict__ bb,
                      __half* __restrict__ C, int M) {
    extern __shared__ uint32_t ws[];
    uint32_t* wsa = ws;            // 8192 u32 (32KB)
    uint32_t* wsb = ws + 8192;     // 8192 u32 (32KB)
    __half* tile = reinterpret_cast<__half*>(ws + 16384);
    const int tid = threadIdx.x;

    {   // stage both weight fragment sets (64KB) once per block
        uint4* d = reinterpret_cast<uint4*>(ws);
        const uint4* sa = reinterpret_cast<const uint4*>(Wfa);
        const uint4* sb = reinterpret_cast<const uint4*>(Wfb);
#pragma unroll
        for (int i = 0; i < 8; i++) d[tid + 256 * i]        = sa[tid + 256 * i];
#pragma unroll
        for (int i = 0; i < 8; i++) d[2048 + tid + 256 * i] = sb[tid + 256 * i];
    }
    __syncthreads();

    const int warp = tid >> 5, lane = tid & 31;
    const int g = lane >> 2, t = lane & 3;
    const int row0 = blockIdx.x * 256 + warp * 32;   // 32 rows per warp
    const int r0 = row0 + g;
    const int r1 = r0 + 8;
    const int r2 = r0 + 16;
    const int r3 = r0 + 24;
    const __half* A0 = A + (size_t)min(r0, M - 1) * 128;
    const __half* A1 = A + (size_t)min(r1, M - 1) * 128;
    const __half* A2 = A + (size_t)min(r2, M - 1) * 128;
    const __half* A3 = A + (size_t)min(r3, M - 1) * 128;
    __half* tw = tile + warp * (32 * T_STRIDE);

    float acc0[16][4], acc1[16][4];
#pragma unroll
    for (int i = 0; i < 16; i++)
#pragma unroll
        for (int j = 0; j < 4; j++) { acc0[i][j] = 0.f; acc1[i][j] = 0.f; }

    // ---- GEMM 1: both tiles share each (b0,b1); A software-pipelined ----
    uint32_t na[8];
    {
        int kb = 2 * t;
        na[0] = *reinterpret_cast<const uint32_t*>(A0 + kb);
        na[1] = *reinterpret_cast<const uint32_t*>(A1 + kb);
        na[2] = *reinterpret_cast<const uint32_t*>(A0 + kb + 8);
        na[3] = *reinterpret_cast<const uint32_t*>(A1 + kb + 8);
        na[4] = *reinterpret_cast<const uint32_t*>(A2 + kb);
        na[5] = *reinterpret_cast<const uint32_t*>(A3 + kb);
        na[6] = *reinterpret_cast<const uint32_t*>(A2 + kb + 8);
        na[7] = *reinterpret_cast<const uint32_t*>(A3 + kb + 8);
    }
#pragma unroll
    for (int kt = 0; kt < 8; kt++) {
        uint32_t a[8];
#pragma unroll
        for (int i = 0; i < 8; i++) a[i] = na[i];
        if (kt < 7) {
            int kb = (kt + 1) * 16 + 2 * t;
            na[0] = *reinterpret_cast<const uint32_t*>(A0 + kb);
            na[1] = *reinterpret_cast<const uint32_t*>(A1 + kb);
            na[2] = *reinterpret_cast<const uint32_t*>(A0 + kb + 8);
            na[3] = *reinterpret_cast<const uint32_t*>(A1 + kb + 8);
            na[4] = *reinterpret_cast<const uint32_t*>(A2 + kb);
            na[5] = *reinterpret_cast<const uint32_t*>(A3 + kb);
            na[6] = *reinterpret_cast<const uint32_t*>(A2 + kb + 8);
            na[7] = *reinterpret_cast<const uint32_t*>(A3 + kb + 8);
        }
        const uint32_t* wbase = wsa + kt * 1024;
#pragma unroll
        for (int nt = 0; nt < 16; nt++) {
            uint32_t b0 = wbase[nt * 64 + lane];
            uint32_t b1 = wbase[nt * 64 + 32 + lane];
            mma_f16(acc0[nt], a[0], a[1], a[2], a[3], b0, b1);
            mma_f16(acc1[nt], a[4], a[5], a[6], a[7], b0, b1);
        }
    }

    // ---- t = relu(acc + ba) -> warp-private fp16 smem tile (32 rows) ----
#pragma unroll
    for (int nt = 0; nt < 16; nt++) {
        int col = nt * 8 + 2 * t;
        float bx = ba[col], by = ba[col + 1];
        __half2 o00 = __floats2half2_rn(fmaxf(acc0[nt][0] + bx, 0.f),
                                        fmaxf(acc0[nt][1] + by, 0.f));
        __half2 o01 = __floats2half2_rn(fmaxf(acc0[nt][2] + bx, 0.f),
                                        fmaxf(acc0[nt][3] + by, 0.f));
        __half2 o10 = __floats2half2_rn(fmaxf(acc1[nt][0] + bx, 0.f),
                                        fmaxf(acc1[nt][1] + by, 0.f));
        __half2 o11 = __floats2half2_rn(fmaxf(acc1[nt][2] + bx, 0.f),
                                        fmaxf(acc1[nt][3] + by, 0.f));
        *reinterpret_cast<__half2*>(tw + g * T_STRIDE + col)        = o00;
        *reinterpret_cast<__half2*>(tw + (g + 8) * T_STRIDE + col)  = o01;
        *reinterpret_cast<__half2*>(tw + (g + 16) * T_STRIDE + col) = o10;
        *reinterpret_cast<__half2*>(tw + (g + 24) * T_STRIDE + col) = o11;
    }
    __syncwarp();

    // ---- GEMM 2: acc = t @ Wb (shared b across both tiles) ----
#pragma unroll
    for (int i = 0; i < 16; i++)
#pragma unroll
        for (int j = 0; j < 4; j++) { acc0[i][j] = 0.f; acc1[i][j] = 0.f; }

#pragma unroll
    for (int kt = 0; kt < 8; kt++) {
        int kb = kt * 16 + 2 * t;
        uint32_t a0 = *reinterpret_cast<const uint32_t*>(tw + g * T_STRIDE + kb);
        uint32_t a1 = *reinterpret_cast<const uint32_t*>(tw + (g + 8) * T_STRIDE + kb);
        uint32_t a2 = *reinterpret_cast<const uint32_t*>(tw + g * T_STRIDE + kb + 8);
        uint32_t a3 = *reinterpret_cast<const uint32_t*>(tw + (g + 8) * T_STRIDE + kb + 8);
        uint32_t a4 = *reinterpret_cast<const uint32_t*>(tw + (g + 16) * T_STRIDE + kb);
        uint32_t a5 = *reinterpret_cast<const uint32_t*>(tw + (g + 24) * T_STRIDE + kb);
        uint32_t a6 = *reinterpret_cast<const uint32_t*>(tw + (g + 16) * T_STRIDE + kb + 8);
        uint32_t a7 = *reinterpret_cast<const uint32_t*>(tw + (g + 24) * T_STRIDE + kb + 8);
        const uint32_t* wbase = wsb + kt * 1024;
#pragma unroll
        for (int nt = 0; nt < 16; nt++) {
            uint32_t b0 = wbase[nt * 64 + lane];
            uint32_t b1 = wbase[nt * 64 + 32 + lane];
            mma_f16(acc0[nt], a0, a1, a2, a3, b0, b1);
            mma_f16(acc1[nt], a4, a5, a6, a7, b0, b1);
        }
    }

    // ---- C = relu(acc + bb) -> fp16 ----
#pragma unroll
    for (int nt = 0; nt < 16; nt++) {
        int col = nt * 8 + 2 * t;
        float bx = bb[col], by = bb[col + 1];
        if (r0 < M) {
            __half2 o = __floats2half2_rn(fmaxf(acc0[nt][0] + bx, 0.f),
                                          fmaxf(acc0[nt][1] + by, 0.f));
            *reinterpret_cast<__half2*>(C + (size_t)r0 * 128 + col) = o;
        }
        if (r1 < M) {
            __half2 o = __floats2half2_rn(fmaxf(acc0[nt][2] + bx, 0.f),
                                          fmaxf(acc0[nt][3] + by, 0.f));
            *reinterpret_cast<__half2*>(C + (size_t)r1 * 128 + col) = o;
        }
        if (r2 < M) {
            __half2 o = __floats2half2_rn(fmaxf(acc1[nt][0] + bx, 0.f),
                                          fmaxf(acc1[nt][1] + by, 0.f));
            *reinterpret_cast<__half2*>(C + (size_t)r2 * 128 + col) = o;
        }
        if (r3 < M) {
            __half2 o = __floats2half2_rn(fmaxf(acc1[nt][2] + bx, 0.f),
                                          fmaxf(acc1[nt][3] + by, 0.f));
            *reinterpret_cast<__half2*>(C + (size_t)r3 * 128 + col) = o;
        }
    }
}

// ---------------- fused pool + classifier head + log_softmax ------------------
__device__ __forceinline__ int lower_bound_batch(const void* batch, int N, int val) {
    int lo = 0, hi = N;
    while (lo < hi) {
        int mid = (lo + hi) >> 1;
        if (load_idx(batch, mid) < val) lo = mid + 1; else hi = mid;
    }
    return lo;
}

__global__ void head_kernel(const __half* __restrict__ h, const void* __restrict__ batch,
                            int N,
                            const float* __restrict__ Wl1, const float* __restrict__ bl1,
                            const float* __restrict__ Wl2, const float* __restrict__ bl2,
                            float* __restrict__ out) {
    __shared__ float row[128];
    __shared__ float hid[128];
    __shared__ float lg[10];
    __shared__ float red[2];
    int gi = blockIdx.x;
    int t = threadIdx.x;

    int s = lower_bound_batch(batch, N, gi);
    int e = lower_bound_batch(batch, N, gi + 1);
    float sum = 0.f;
    for (int n = s; n < e; n++) sum += __half2float(h[(size_t)n * 128 + t]);
    row[t] = sum;
    __syncthreads();

    float v1 = bl1[t];
#pragma unroll 8
    for (int k = 0; k < 128; k++) v1 += row[k] * Wl1[k * 128 + t];
    hid[t] = fmaxf(v1, 0.f);
    __syncthreads();

    if (t < 10) {
        float v = bl2[t];
#pragma unroll 8
        for (int k = 0; k < 128; k++) v += hid[k] * Wl2[k * 10 + t];
        lg[t] = v;
    }
    __syncthreads();

    if (t == 0) {
        float m = lg[0];
        for (int i = 1; i < 10; i++) m = fmaxf(m, lg[i]);
        float se = 0.f;
        for (int i = 0; i < 10; i++) se += expf(lg[i] - m);
        red[0] = m;
        red[1] = logf(se);
    }
    __syncthreads();

    if (t < 10) out[(size_t)gi * 10 + t] = lg[t] - red[0] - red[1];
}

// ---------------- launch ------------------------------------------------------
extern "C" void kernel_launch(void* const* d_in, const int* in_sizes, int n_in,
                              void* d_out, int out_size) {
    const float* x     = (const float*)d_in[0];
    const void*  ei    = d_in[1];
    const void*  batch = d_in[2];
    const float* W1a = (const float*)d_in[3];
    const float* b1a = (const float*)d_in[4];
    const float* W1b = (const float*)d_in[5];
    const float* b1b = (const float*)d_in[6];
    const float* W2a = (const float*)d_in[7];
    const float* b2a = (const float*)d_in[8];
    const float* W2b = (const float*)d_in[9];
    const float* b2b = (const float*)d_in[10];
    const float* Wl1 = (const float*)d_in[11];
    const float* bl1 = (const float*)d_in[12];
    const float* Wl2 = (const float*)d_in[13];
    const float* bl2 = (const float*)d_in[14];
    float* out = (float*)d_out;

    const int N = in_sizes[0] / 128;
    const int E = in_sizes[1] / 2;

    __half *xh, *aggh, *h1, *h2;
    uint32_t *wf;
    int *deg, *rowptr, *cursor, *csr, *bsum, *boff;
    cudaGetSymbolAddress((void**)&xh,     g_xh);
    cudaGetSymbolAddress((void**)&aggh,   g_agg);
    cudaGetSymbolAddress((void**)&h1,     g_h1);
    cudaGetSymbolAddress((void**)&h2,     g_h2);
    cudaGetSymbolAddress((void**)&deg,    g_deg);
    cudaGetSymbolAddress((void**)&rowptr, g_rowptr);
    cudaGetSymbolAddress((void**)&cursor, g_cursor);
    cudaGetSymbolAddress((void**)&csr,    g_csr);
    cudaGetSymbolAddress((void**)&bsum,   g_bsum);
    cudaGetSymbolAddress((void**)&boff,   g_boff);
    cudaGetSymbolAddress((void**)&wf,     g_wf16);

    static bool smem_set = false;
    if (!smem_set) {
        cudaFuncSetAttribute(mlp_fused_kernel,
                             cudaFuncAttributeMaxDynamicSharedMemorySize, MLP_SMEM_BYTES);
        smem_set = true;
    }

    const int edge4Blks  = ((E + 3) / 4 + 255) / 256;   // 4 edges per thread
    const int gatherBlks = (N * 32 + 255) / 256;        // one warp per node
    const int gemmBlks   = (N + 255) / 256;             // 256 rows per block (32/warp)
    const int CH         = (N + 127) / 128;
    const int prepBlks   = (32768 + N * 64 + N + 1 + 255) / 256;

    detect_kernel<<<1, 256>>>((const unsigned int*)ei, (long long)in_sizes[1]);

    // merged: 4 weight transforms + x -> fp16 + deg zeroing
    prep_kernel<<<prepBlks, 256>>>(x, xh, N * 64, W1a, W1b, W2a, W2b, wf, deg, N + 1);

    // ---- CSR build (vectorized, no intermediates) ----
    hist_kernel<<<edge4Blks, 256>>>(ei, E, deg);
    scan_partial_kernel<<<128, 256>>>(deg, N, CH, bsum);
    scan_bsum_kernel<<<1, 128>>>(bsum, boff, rowptr, N);
    scan_write_kernel<<<128, 256>>>(deg, N, CH, boff, rowptr, cursor);
    fill_kernel<<<edge4Blks, 256>>>(ei, E, cursor, csr);

    // ---- layer 1: xh -> aggh -> h1 ----
    gather_kernel<<<gatherBlks, 256>>>(xh, csr, rowptr, N, aggh);
    mlp_fused_kernel<<<gemmBlks, 256, MLP_SMEM_BYTES>>>(
        aggh, wf + 0 * 8192, wf + 1 * 8192, b1a, b1b, h1, N);

    // ---- layer 2: h1 -> aggh -> h2 ----
    gather_kernel<<<gatherBlks, 256>>>(h1, csr, rowptr, N, aggh);
    mlp_fused_kernel<<<gemmBlks, 256, MLP_SMEM_BYTES>>>(
        aggh, wf + 2 * 8192, wf + 3 * 8192, b2a, b2b, h2, N);

    // ---- fused pool + head ----
    head_kernel<<<1024, 128>>>(h2, batch, N, Wl1, bl1, Wl2, bl2, out);
}

// round 16
// speedup vs baseline: 1.0349x; 1.0349x over previous
#include <cuda_runtime.h>
#include <cuda_fp16.h>
#include <cstdint>

// ---------------- scratch (static device globals; no allocation) ------------
__device__ __half g_xh [(size_t)100000 * 128];
__device__ __half g_agg[(size_t)100000 * 128];
__device__ __half g_h1 [(size_t)100000 * 128];
__device__ __half g_h2 [(size_t)100000 * 128];
__device__ int   g_deg   [100002];
__device__ int   g_rowptr[100002];
__device__ int   g_cursor[100002];
__device__ int   g_csr   [1700000];
__device__ int   g_bsum  [128];
__device__ uint32_t g_wf16[4][8192];   // fragment-ready fp16 weights (half2 packed)
__device__ int   g_idx64;

// ---------------- index dtype detection (parallel) ---------------------------
__global__ void detect_kernel(const unsigned int* __restrict__ w, long long n32) {
    long long nelem = n32 / 2;
    int t = threadIdx.x;
    long long e = ((long long)t * (nelem - 1)) / 255;
    int ok = (t < 256) ? (w[2 * e + 1] == 0u) : 1;
    int all = __syncthreads_and(ok);
    if (t == 0) g_idx64 = all ? 1 : 0;
}

__device__ __forceinline__ int load_idx(const void* p, long long i) {
    if (g_idx64) return (int)((const long long*)p)[i];
    return ((const int*)p)[i];
}

// ---------------- merged prep: wtransform + x->fp16 + deg zero ----------------
__global__ void prep_kernel(const float* __restrict__ x, __half* __restrict__ xh, int n2,
                            const float* __restrict__ W0, const float* __restrict__ W1,
                            const float* __restrict__ W2, const float* __restrict__ W3,
                            uint32_t* __restrict__ Wf, int* __restrict__ deg, int ndeg) {
    int gid = blockIdx.x * blockDim.x + threadIdx.x;
    if (gid < 32768) {
        int which = gid >> 13;
        int o = gid & 8191;
        const float* W = (which == 0) ? W0 : (which == 1) ? W1 : (which == 2) ? W2 : W3;
        int lane = o & 31;
        int r    = (o >> 5) & 1;
        int nt   = (o >> 6) & 15;
        int kt   = o >> 10;
        int c = lane >> 2, t = lane & 3;
        int k = kt * 16 + 2 * t + 8 * r;
        int n = nt * 8 + c;
        __half2 v = __floats2half2_rn(W[k * 128 + n], W[(k + 1) * 128 + n]);
        Wf[gid] = *reinterpret_cast<uint32_t*>(&v);
    } else if (gid < 32768 + n2) {
        int i = gid - 32768;
        float2 v = reinterpret_cast<const float2*>(x)[i];
        reinterpret_cast<__half2*>(xh)[i] = __floats2half2_rn(v.x, v.y);
    } else {
        int i = gid - 32768 - n2;
        if (i < ndeg) deg[i] = 0;
    }
}

// ---------------- CSR build ---------------------------------------------------
__global__ void hist_kernel(const void* __restrict__ ei, int E, int* __restrict__ deg) {
    int i = (blockIdx.x * blockDim.x + threadIdx.x) * 4;
    if (i >= E) return;
    if (i + 4 <= E) {
        int d[4];
        if (g_idx64) {
            const longlong2* pd = reinterpret_cast<const longlong2*>((const long long*)ei + E + i);
            longlong2 d01 = pd[0], d23 = pd[1];
            d[0] = (int)d01.x; d[1] = (int)d01.y; d[2] = (int)d23.x; d[3] = (int)d23.y;
        } else {
            int4 dv = *reinterpret_cast<const int4*>((const int*)ei + E + i);
            d[0] = dv.x; d[1] = dv.y; d[2] = dv.z; d[3] = dv.w;
        }
#pragma unroll
        for (int k = 0; k < 4; k++) atomicAdd(&deg[d[k]], 1);
    } else {
        for (int k = 0; i + k < E; k++)
            atomicAdd(&deg[load_idx(ei, (long long)E + i + k)], 1);
    }
}

__global__ void scan_partial_kernel(const int* __restrict__ deg, int N, int CH,
                                    int* __restrict__ bsum) {
    __shared__ int red[256];
    int b = blockIdx.x, t = threadIdx.x;
    int s = b * CH, e = min(s + CH, N);
    int sum = 0;
    for (int i = s + t; i < e; i += 256) sum += deg[i];
    red[t] = sum;
    __syncthreads();
    for (int off = 128; off > 0; off >>= 1) {
        if (t < off) red[t] += red[t + off];
        __syncthreads();
    }
    if (t == 0) bsum[b] = red[0];
}

// merged: each block locally scans the 128 bsums, then writes its chunk
__global__ void scan_write_kernel(const int* __restrict__ deg, int N, int CH,
                                  const int* __restrict__ bsum,
                                  int* __restrict__ rowptr, int* __restrict__ cursor) {
    __shared__ int bs[128];
    __shared__ int ts[256];
    int b = blockIdx.x, t = threadIdx.x;

    if (t < 128) bs[t] = bsum[t];
    __syncthreads();
    if (t == 0) {
        int run = 0;
        for (int i = 0; i < 128; i++) { int v = bs[i]; bs[i] = run; run += v; }
        bs[0] = run;   // total stashed; boff for block 0 is 0 anyway
    }
    __syncthreads();
    int boff = (b == 0) ? 0 : bs[b];
    if (b == 127 && t == 0) rowptr[N] = bs[0] == 0 && N > 0 ? bs[0] : bs[0];  // total
    // note: bs[0] holds the grand total after the serial pass

    int s = b * CH, e = min(s + CH, N);
    int tc = (CH + 255) / 256;
    int ms = s + t * tc, me = min(ms + tc, e);
    int sum = 0;
    for (int i = ms; i < me; i++) sum += deg[i];
    ts[t] = sum;
    __syncthreads();
    for (int off = 1; off < 256; off <<= 1) {
        int v = (t >= off) ? ts[t - off] : 0;
        __syncthreads();
        ts[t] += v;
        __syncthreads();
    }
    int run = boff + ((t == 0) ? 0 : ts[t - 1]);
    for (int i = ms; i < me; i++) {
        rowptr[i] = run;
        cursor[i] = run;
        run += deg[i];
    }
}

__global__ void fill_kernel(const void* __restrict__ ei, int E,
                            int* __restrict__ cursor, int* __restrict__ csr) {
    int i = (blockIdx.x * blockDim.x + threadIdx.x) * 4;
    if (i >= E) return;
    if (i + 4 <= E) {
        int s[4], d[4];
        if (g_idx64) {
            const longlong2* ps = reinterpret_cast<const longlong2*>((const long long*)ei + i);
            const longlong2* pd = reinterpret_cast<const longlong2*>((const long long*)ei + E + i);
            longlong2 s01 = ps[0], s23 = ps[1];
            longlong2 d01 = pd[0], d23 = pd[1];
            s[0] = (int)s01.x; s[1] = (int)s01.y; s[2] = (int)s23.x; s[3] = (int)s23.y;
            d[0] = (int)d01.x; d[1] = (int)d01.y; d[2] = (int)d23.x; d[3] = (int)d23.y;
        } else {
            int4 sv = *reinterpret_cast<const int4*>((const int*)ei + i);
            int4 dv = *reinterpret_cast<const int4*>((const int*)ei + E + i);
            s[0] = sv.x; s[1] = sv.y; s[2] = sv.z; s[3] = sv.w;
            d[0] = dv.x; d[1] = dv.y; d[2] = dv.z; d[3] = dv.w;
        }
#pragma unroll
        for (int k = 0; k < 4; k++)
            csr[atomicAdd(&cursor[d[k]], 1)] = s[k];
    } else {
        for (int k = 0; i + k < E; k++) {
            int sv = load_idx(ei, i + k);
            int dv = load_idx(ei, (long long)E + i + k);
            csr[atomicAdd(&cursor[dv], 1)] = sv;
        }
    }
}

// ---------------- gather (fp16, 2 nodes/warp, 16B lane loads) ------------------
__device__ __forceinline__ void ld16B_acc(const __half* p, float* acc) {
    uint4 u = *reinterpret_cast<const uint4*>(p);
    const __half2* h2 = reinterpret_cast<const __half2*>(&u);
#pragma unroll
    for (int i = 0; i < 4; i++) {
        float2 f = __half22float2(h2[i]);
        acc[2 * i]     += f.x;
        acc[2 * i + 1] += f.y;
    }
}

__global__ void gather_kernel(const __half* __restrict__ h, const int* __restrict__ csr,
                              const int* __restrict__ rowptr, int N,
                              __half* __restrict__ out) {
    int w = (blockIdx.x * blockDim.x + threadIdx.x) >> 5;
    int lane = threadIdx.x & 31;
    int node = w * 2 + (lane >> 4);
    if (node >= N) return;
    int q = (lane & 15) * 8;   // 8 halves = 16B per lane; 16 lanes = 256B row

    float acc[8] = {0.f, 0.f, 0.f, 0.f, 0.f, 0.f, 0.f, 0.f};
    ld16B_acc(h + (size_t)node * 128 + q, acc);   // self (eps = 0)

    int s = rowptr[node];
    int e = rowptr[node + 1];
    int j = s;
    for (; j + 4 <= e; j += 4) {
        int n0 = csr[j], n1 = csr[j + 1], n2 = csr[j + 2], n3 = csr[j + 3];
        ld16B_acc(h + (size_t)n0 * 128 + q, acc);
        ld16B_acc(h + (size_t)n1 * 128 + q, acc);
        ld16B_acc(h + (size_t)n2 * 128 + q, acc);
        ld16B_acc(h + (size_t)n3 * 128 + q, acc);
    }
    for (; j < e; j++) ld16B_acc(h + (size_t)csr[j] * 128 + q, acc);

    uint4 o;
    __half2* oh = reinterpret_cast<__half2*>(&o);
#pragma unroll
    for (int i = 0; i < 4; i++) oh[i] = __floats2half2_rn(acc[2 * i], acc[2 * i + 1]);
    *reinterpret_cast<uint4*>(out + (size_t)node * 128 + q) = o;
}

// ---------------- fused MLP (fp16 MMA, 32 rows/warp, B-fragment reuse) --------
__device__ __forceinline__ void mma_f16(float* c, uint32_t a0, uint32_t a1,
                                        uint32_t a2, uint32_t a3,
                                        uint32_t b0, uint32_t b1) {
    asm volatile(
        "mma.sync.aligned.m16n8k16.row.col.f32.f16.f16.f32 "
        "{%0,%1,%2,%3}, {%4,%5,%6,%7}, {%8,%9}, {%0,%1,%2,%3};"
        : "+f"(c[0]), "+f"(c[1]), "+f"(c[2]), "+f"(c[3])
        : "r"(a0), "r"(a1), "r"(a2), "r"(a3), "r"(b0), "r"(b1));
}

#define T_STRIDE 136
#define MLP_SMEM_BYTES (32768 + 32768 + 8 * 32 * T_STRIDE * 2)

__global__ __launch_bounds__(256, 1)
void mlp_fused_kernel(const __half* __restrict__ A,
                      const uint32_t* __restrict__ Wfa, const uint32_t* __restrict__ Wfb,
                      const float* __restrict__ ba, const float* __restrict__ bb,
                      __half* __restrict__ C, int M) {
    extern __shared__ uint32_t ws[];
    uint32_t* wsa = ws;            // 8192 u32 (32KB)
    uint32_t* wsb = ws + 8192;     // 8192 u32 (32KB)
    __half* tile = reinterpret_cast<__half*>(ws + 16384);
    const int tid = threadIdx.x;

    {   // stage both weight fragment sets (64KB) once per block
        uint4* d = reinterpret_cast<uint4*>(ws);
        const uint4* sa = reinterpret_cast<const uint4*>(Wfa);
        const uint4* sb = reinterpret_cast<const uint4*>(Wfb);
#pragma unroll
        for (int i = 0; i < 8; i++) d[tid + 256 * i]        = sa[tid + 256 * i];
#pragma unroll
        for (int i = 0; i < 8; i++) d[2048 + tid + 256 * i] = sb[tid + 256 * i];
    }
    __syncthreads();

    const int warp = tid >> 5, lane = tid & 31;
    const int g = lane >> 2, t = lane & 3;
    const int row0 = blockIdx.x * 256 + warp * 32;   // 32 rows per warp
    const int r0 = row0 + g;
    const int r1 = r0 + 8;
    const int r2 = r0 + 16;
    const int r3 = r0 + 24;
    const __half* A0 = A + (size_t)min(r0, M - 1) * 128;
    const __half* A1 = A + (size_t)min(r1, M - 1) * 128;
    const __half* A2 = A + (size_t)min(r2, M - 1) * 128;
    const __half* A3 = A + (size_t)min(r3, M - 1) * 128;
    __half* tw = tile + warp * (32 * T_STRIDE);

    float acc0[16][4], acc1[16][4];
#pragma unroll
    for (int i = 0; i < 16; i++)
#pragma unroll
        for (int j = 0; j < 4; j++) { acc0[i][j] = 0.f; acc1[i][j] = 0.f; }

    // ---- GEMM 1: both tiles share each (b0,b1); A software-pipelined ----
    uint32_t na[8];
    {
        int kb = 2 * t;
        na[0] = *reinterpret_cast<const uint32_t*>(A0 + kb);
        na[1] = *reinterpret_cast<const uint32_t*>(A1 + kb);
        na[2] = *reinterpret_cast<const uint32_t*>(A0 + kb + 8);
        na[3] = *reinterpret_cast<const uint32_t*>(A1 + kb + 8);
        na[4] = *reinterpret_cast<const uint32_t*>(A2 + kb);
        na[5] = *reinterpret_cast<const uint32_t*>(A3 + kb);
        na[6] = *reinterpret_cast<const uint32_t*>(A2 + kb + 8);
        na[7] = *reinterpret_cast<const uint32_t*>(A3 + kb + 8);
    }
#pragma unroll
    for (int kt = 0; kt < 8; kt++) {
        uint32_t a[8];
#pragma unroll
        for (int i = 0; i < 8; i++) a[i] = na[i];
        if (kt < 7) {
            int kb = (kt + 1) * 16 + 2 * t;
            na[0] = *reinterpret_cast<const uint32_t*>(A0 + kb);
            na[1] = *reinterpret_cast<const uint32_t*>(A1 + kb);
            na[2] = *reinterpret_cast<const uint32_t*>(A0 + kb + 8);
            na[3] = *reinterpret_cast<const uint32_t*>(A1 + kb + 8);
            na[4] = *reinterpret_cast<const uint32_t*>(A2 + kb);
            na[5] = *reinterpret_cast<const uint32_t*>(A3 + kb);
            na[6] = *reinterpret_cast<const uint32_t*>(A2 + kb + 8);
            na[7] = *reinterpret_cast<const uint32_t*>(A3 + kb + 8);
        }
        const uint32_t* wbase = wsa + kt * 1024;
#pragma unroll
        for (int nt = 0; nt < 16; nt++) {
            uint32_t b0 = wbase[nt * 64 + lane];
            uint32_t b1 = wbase[nt * 64 + 32 + lane];
            mma_f16(acc0[nt], a[0], a[1], a[2], a[3], b0, b1);
            mma_f16(acc1[nt], a[4], a[5], a[6], a[7], b0, b1);
        }
    }

    // ---- t = relu(acc + ba) -> warp-private fp16 smem tile (32 rows) ----
#pragma unroll
    for (int nt = 0; nt < 16; nt++) {
        int col = nt * 8 + 2 * t;
        float bx = ba[col], by = ba[col + 1];
        __half2 o00 = __floats2half2_rn(fmaxf(acc0[nt][0] + bx, 0.f),
                                        fmaxf(acc0[nt][1] + by, 0.f));
        __half2 o01 = __floats2half2_rn(fmaxf(acc0[nt][2] + bx, 0.f),
                                        fmaxf(acc0[nt][3] + by, 0.f));
        __half2 o10 = __floats2half2_rn(fmaxf(acc1[nt][0] + bx, 0.f),
                                        fmaxf(acc1[nt][1] + by, 0.f));
        __half2 o11 = __floats2half2_rn(fmaxf(acc1[nt][2] + bx, 0.f),
                                        fmaxf(acc1[nt][3] + by, 0.f));
        *reinterpret_cast<__half2*>(tw + g * T_STRIDE + col)        = o00;
        *reinterpret_cast<__half2*>(tw + (g + 8) * T_STRIDE + col)  = o01;
        *reinterpret_cast<__half2*>(tw + (g + 16) * T_STRIDE + col) = o10;
        *reinterpret_cast<__half2*>(tw + (g + 24) * T_STRIDE + col) = o11;
    }
    __syncwarp();

    // ---- GEMM 2: acc = t @ Wb (shared b across both tiles) ----
#pragma unroll
    for (int i = 0; i < 16; i++)
#pragma unroll
        for (int j = 0; j < 4; j++) { acc0[i][j] = 0.f; acc1[i][j] = 0.f; }

#pragma unroll
    for (int kt = 0; kt < 8; kt++) {
        int kb = kt * 16 + 2 * t;
        uint32_t a0 = *reinterpret_cast<const uint32_t*>(tw + g * T_STRIDE + kb);
        uint32_t a1 = *reinterpret_cast<const uint32_t*>(tw + (g + 8) * T_STRIDE + kb);
        uint32_t a2 = *reinterpret_cast<const uint32_t*>(tw + g * T_STRIDE + kb + 8);
        uint32_t a3 = *reinterpret_cast<const uint32_t*>(tw + (g + 8) * T_STRIDE + kb + 8);
        uint32_t a4 = *reinterpret_cast<const uint32_t*>(tw + (g + 16) * T_STRIDE + kb);
        uint32_t a5 = *reinterpret_cast<const uint32_t*>(tw + (g + 24) * T_STRIDE + kb);
        uint32_t a6 = *reinterpret_cast<const uint32_t*>(tw + (g + 16) * T_STRIDE + kb + 8);
        uint32_t a7 = *reinterpret_cast<const uint32_t*>(tw + (g + 24) * T_STRIDE + kb + 8);
        const uint32_t* wbase = wsb + kt * 1024;
#pragma unroll
        for (int nt = 0; nt < 16; nt++) {
            uint32_t b0 = wbase[nt * 64 + lane];
            uint32_t b1 = wbase[nt * 64 + 32 + lane];
            mma_f16(acc0[nt], a0, a1, a2, a3, b0, b1);
            mma_f16(acc1[nt], a4, a5, a6, a7, b0, b1);
        }
    }

    // ---- C = relu(acc + bb) -> fp16 ----
#pragma unroll
    for (int nt = 0; nt < 16; nt++) {
        int col = nt * 8 + 2 * t;
        float bx = bb[col], by = bb[col + 1];
        if (r0 < M) {
            __half2 o = __floats2half2_rn(fmaxf(acc0[nt][0] + bx, 0.f),
                                          fmaxf(acc0[nt][1] + by, 0.f));
            *reinterpret_cast<__half2*>(C + (size_t)r0 * 128 + col) = o;
        }
        if (r1 < M) {
            __half2 o = __floats2half2_rn(fmaxf(acc0[nt][2] + bx, 0.f),
                                          fmaxf(acc0[nt][3] + by, 0.f));
            *reinterpret_cast<__half2*>(C + (size_t)r1 * 128 + col) = o;
        }
        if (r2 < M) {
            __half2 o = __floats2half2_rn(fmaxf(acc1[nt][0] + bx, 0.f),
                                          fmaxf(acc1[nt][1] + by, 0.f));
            *reinterpret_cast<__half2*>(C + (size_t)r2 * 128 + col) = o;
        }
        if (r3 < M) {
            __half2 o = __floats2half2_rn(fmaxf(acc1[nt][2] + bx, 0.f),
                                          fmaxf(acc1[nt][3] + by, 0.f));
            *reinterpret_cast<__half2*>(C + (size_t)r3 * 128 + col) = o;
        }
    }
}

// ---------------- fused pool + classifier head + log_softmax ------------------
__device__ __forceinline__ int lower_bound_batch(const void* batch, int N, int val) {
    int lo = 0, hi = N;
    while (lo < hi) {
        int mid = (lo + hi) >> 1;
        if (load_idx(batch, mid) < val) lo = mid + 1; else hi = mid;
    }
    return lo;
}

__global__ void head_kernel(const __half* __restrict__ h, const void* __restrict__ batch,
                            int N,
                            const float* __restrict__ Wl1, const float* __restrict__ bl1,
                            const float* __restrict__ Wl2, const float* __restrict__ bl2,
                            float* __restrict__ out) {
    __shared__ float row[128];
    __shared__ float hid[128];
    __shared__ float lg[10];
    __shared__ float red[2];
    int gi = blockIdx.x;
    int t = threadIdx.x;

    int s = lower_bound_batch(batch, N, gi);
    int e = lower_bound_batch(batch, N, gi + 1);
    float sum = 0.f;
    for (int n = s; n < e; n++) sum += __half2float(h[(size_t)n * 128 + t]);
    row[t] = sum;
    __syncthreads();

    float v1 = bl1[t];
#pragma unroll 8
    for (int k = 0; k < 128; k++) v1 += row[k] * Wl1[k * 128 + t];
    hid[t] = fmaxf(v1, 0.f);
    __syncthreads();

    if (t < 10) {
        float v = bl2[t];
#pragma unroll 8
        for (int k = 0; k < 128; k++) v += hid[k] * Wl2[k * 10 + t];
        lg[t] = v;
    }
    __syncthreads();

    if (t == 0) {
        float m = lg[0];
        for (int i = 1; i < 10; i++) m = fmaxf(m, lg[i]);
        float se = 0.f;
        for (int i = 0; i < 10; i++) se += expf(lg[i] - m);
        red[0] = m;
        red[1] = logf(se);
    }
    __syncthreads();

    if (t < 10) out[(size_t)gi * 10 + t] = lg[t] - red[0] - red[1];
}

// ---------------- launch ------------------------------------------------------
extern "C" void kernel_launch(void* const* d_in, const int* in_sizes, int n_in,
                              void* d_out, int out_size) {
    const float* x     = (const float*)d_in[0];
    const void*  ei    = d_in[1];
    const void*  batch = d_in[2];
    const float* W1a = (const float*)d_in[3];
    const float* b1a = (const float*)d_in[4];
    const float* W1b = (const float*)d_in[5];
    const float* b1b = (const float*)d_in[6];
    const float* W2a = (const float*)d_in[7];
    const float* b2a = (const float*)d_in[8];
    const float* W2b = (const float*)d_in[9];
    const float* b2b = (const float*)d_in[10];
    const float* Wl1 = (const float*)d_in[11];
    const float* bl1 = (const float*)d_in[12];
    const float* Wl2 = (const float*)d_in[13];
    const float* bl2 = (const float*)d_in[14];
    float* out = (float*)d_out;

    const int N = in_sizes[0] / 128;
    const int E = in_sizes[1] / 2;

    __half *xh, *aggh, *h1, *h2;
    uint32_t *wf;
    int *deg, *rowptr, *cursor, *csr, *bsum;
    cudaGetSymbolAddress((void**)&xh,     g_xh);
    cudaGetSymbolAddress((void**)&aggh,   g_agg);
    cudaGetSymbolAddress((void**)&h1,     g_h1);
    cudaGetSymbolAddress((void**)&h2,     g_h2);
    cudaGetSymbolAddress((void**)&deg,    g_deg);
    cudaGetSymbolAddress((void**)&rowptr, g_rowptr);
    cudaGetSymbolAddress((void**)&cursor, g_cursor);
    cudaGetSymbolAddress((void**)&csr,    g_csr);
    cudaGetSymbolAddress((void**)&bsum,   g_bsum);
    cudaGetSymbolAddress((void**)&wf,     g_wf16);

    static bool smem_set = false;
    if (!smem_set) {
        cudaFuncSetAttribute(mlp_fused_kernel,
                             cudaFuncAttributeMaxDynamicSharedMemorySize, MLP_SMEM_BYTES);
        smem_set = true;
    }

    const int edge4Blks  = ((E + 3) / 4 + 255) / 256;      // 4 edges per thread
    const int gatherBlks = (((N + 1) / 2) * 32 + 255) / 256;  // 2 nodes per warp
    const int gemmBlks   = (N + 255) / 256;
    const int CH         = (N + 127) / 128;
    const int prepBlks   = (32768 + N * 64 + N + 1 + 255) / 256;

    detect_kernel<<<1, 256>>>((const unsigned int*)ei, (long long)in_sizes[1]);

    // merged: 4 weight transforms + x -> fp16 + deg zeroing
    prep_kernel<<<prepBlks, 256>>>(x, xh, N * 64, W1a, W1b, W2a, W2b, wf, deg, N + 1);

    // ---- CSR build ----
    hist_kernel<<<edge4Blks, 256>>>(ei, E, deg);
    scan_partial_kernel<<<128, 256>>>(deg, N, CH, bsum);
    scan_write_kernel<<<128, 256>>>(deg, N, CH, bsum, rowptr, cursor);
    fill_kernel<<<edge4Blks, 256>>>(ei, E, cursor, csr);

    // ---- layer 1: xh -> aggh -> h1 ----
    gather_kernel<<<gatherBlks, 256>>>(xh, csr, rowptr, N, aggh);
    mlp_fused_kernel<<<gemmBlks, 256, MLP_SMEM_BYTES>>>(
        aggh, wf + 0 * 8192, wf + 1 * 8192, b1a, b1b, h1, N);

    // ---- layer 2: h1 -> aggh -> h2 ----
    gather_kernel<<<gatherBlks, 256>>>(h1, csr, rowptr, N, aggh);
    mlp_fused_kernel<<<gemmBlks, 256, MLP_SMEM_BYTES>>>(
        aggh, wf + 2 * 8192, wf + 3 * 8192, b2a, b2b, h2, N);

    // ---- fused pool + head ----
    head_kernel<<<1024, 128>>>(h2, batch, N, Wl1, bl1, Wl2, bl2, out);
}